// round 3
// baseline (speedup 1.0000x reference)
#include <cuda_runtime.h>

// Problem constants: H=51, L=3, IN=2, B=1024, T=2048
#define Hh   51
#define Gg   204      // 4*H
#define Tt   2048
#define CH   32       // input staging chunk (timesteps)
#define NTH  512      // two independent halves of 256 (batch 0-3 / 4-7)
#define NCTA 128      // 1024 / 8
#define NK0  54       // cell0 fused dot length: 2 (x) + 51 (h0) padded to even
#define NK   102      // cells 1,2 fused dot length: 51 (h_prev) + 51 (h_self)

// ---- shared memory layout (float offsets) ----
#define OFF_W0    0
#define OFF_W1    (OFF_W0 + Gg*NK0)        // 11016
#define OFF_W2    (OFF_W1 + Gg*NK)         // 31824
#define OFF_VBUF  (OFF_W2 + Gg*NK)         // 52632 : 155 rows x 8 = [x(2) | h0(51) | h1(51) | h2(51)]
#define OFF_CBUF  (OFF_VBUF + 155*8)       // 53872 : 153 x 8
#define OFF_GATES (OFF_CBUF + 153*8)       // 55096 : 204 x 8
#define OFF_BIAS  (OFF_GATES + Gg*8)       // 56728 : 612
#define OFF_WLIN  (OFF_BIAS + 612)         // 57340
#define OFF_BLIN  (OFF_WLIN + 102)         // 57442
#define OFF_XS    (OFF_BLIN + 2)           // 57444 : CH x 8 x 2
#define SM_FLOATS (OFF_XS + CH*8*2)        // 57956 floats
#define SM_BYTES  (SM_FLOATS * 4)          // 231824 B <= 232448 limit

__device__ __forceinline__ float sigm_f(float x) {
    return __fdividef(1.0f, 1.0f + __expf(-x));
}
__device__ __forceinline__ float tanh_f(float x) {
    return 1.0f - __fdividef(2.0f, __expf(2.0f * x) + 1.0f);
}

// Duplicate a float into both halves of an f32x2 register
__device__ __forceinline__ unsigned long long dup2(float w) {
    unsigned long long r;
    asm("mov.b64 %0, {%1, %1};" : "=l"(r) : "f"(w));
    return r;
}
// Packed dual-FMA (Blackwell f32x2)
__device__ __forceinline__ unsigned long long fma2(unsigned long long a,
                                                   unsigned long long b,
                                                   unsigned long long c) {
    unsigned long long d;
    asm("fma.rn.f32x2 %0, %1, %2, %3;" : "=l"(d) : "l"(a), "l"(b), "l"(c));
    return d;
}

// per-half named barrier (halves drift independently, sharing only read-only weights)
__device__ __forceinline__ void hbar(int half) {
    asm volatile("bar.sync %0, %1;" :: "r"(half + 1), "r"(256) : "memory");
}

// Fused gate matvec: gates[r][boff..boff+4) = bias + W[r,:] . v[:, boff..boff+4)
// v is [k][8] in smem; 4 batch lanes handled as 2 f32x2 accumulators.
template<int NKc>
__device__ __forceinline__ void matvec2(int r, int boff,
    const float* __restrict__ wrow, const float* __restrict__ v,
    float br, float* __restrict__ gates)
{
    unsigned long long a0 = dup2(br), a1 = a0;
#pragma unroll
    for (int kk = 0; kk < NKc; kk += 2) {
        float2 wp = *(const float2*)(wrow + kk);          // LDS.64, conflict-free (odd 8B stride)
        unsigned long long wd0 = dup2(wp.x);
        unsigned long long wd1 = dup2(wp.y);
        ulonglong2 v0 = *(const ulonglong2*)(v + kk * 8 + boff);       // LDS.128 broadcast
        ulonglong2 v1 = *(const ulonglong2*)(v + (kk + 1) * 8 + boff);
        a0 = fma2(wd0, v0.x, a0);  a1 = fma2(wd0, v0.y, a1);
        a0 = fma2(wd1, v1.x, a0);  a1 = fma2(wd1, v1.y, a1);
    }
    *(ulonglong2*)(gates + r * 8 + boff) = make_ulonglong2(a0, a1);    // STS.128
}

__device__ __forceinline__ void cellupdate(int local, int boff,
    const float* __restrict__ gates, float* __restrict__ cp, float* __restrict__ hp)
{
    if (local < Hh * 4) {
        int jj = local >> 2;
        int bl = (local & 3) + boff;
        float gi = gates[( 0 + jj) * 8 + bl];
        float gf = gates[(51 + jj) * 8 + bl];
        float gg = gates[(102 + jj) * 8 + bl];
        float go = gates[(153 + jj) * 8 + bl];
        float cn = sigm_f(gf) * cp[jj * 8 + bl] + sigm_f(gi) * tanh_f(gg);
        cp[jj * 8 + bl] = cn;
        hp[jj * 8 + bl] = sigm_f(go) * tanh_f(cn);
    }
}

__global__ void __launch_bounds__(NTH, 1) lstm_persistent_kernel(
    const float* __restrict__ g_input, const float* __restrict__ g_time,
    const float* __restrict__ Wih0, const float* __restrict__ Whh0,
    const float* __restrict__ bih0, const float* __restrict__ bhh0,
    const float* __restrict__ Wih1, const float* __restrict__ Whh1,
    const float* __restrict__ bih1, const float* __restrict__ bhh1,
    const float* __restrict__ Wih2, const float* __restrict__ Whh2,
    const float* __restrict__ bih2, const float* __restrict__ bhh2,
    const float* __restrict__ Wlin, const float* __restrict__ blin_g,
    float* __restrict__ out)
{
    extern __shared__ float sm[];
    float* w0    = sm + OFF_W0;
    float* w1    = sm + OFF_W1;
    float* w2    = sm + OFF_W2;
    float* vbuf  = sm + OFF_VBUF;
    float* cbuf  = sm + OFF_CBUF;
    float* gates = sm + OFF_GATES;
    float* bias  = sm + OFF_BIAS;
    float* wlin  = sm + OFF_WLIN;
    float* blin  = sm + OFF_BLIN;
    float* xs    = sm + OFF_XS;

    const int tid   = threadIdx.x;
    const int half  = tid >> 8;        // 0 or 1
    const int local = tid & 255;
    const int boff  = half * 4;        // batch column offset within the 8-wide rows
    const int b0g   = blockIdx.x * 8;

    // ---- build fused weight rows in smem ----
    // w0: [Wih0 | Whh0 | 0-pad] rows of 54
    for (int i = tid; i < Gg * NK0; i += NTH) {
        int r = i / NK0, kk = i % NK0;
        float v = 0.0f;
        if (kk < 2)       v = Wih0[r * 2 + kk];
        else if (kk < 53) v = Whh0[r * 51 + (kk - 2)];
        w0[i] = v;
    }
    // w1/w2: [Wih | Whh] rows of 102
    for (int i = tid; i < Gg * NK; i += NTH) {
        int r = i / NK, kk = i % NK;
        w1[i] = (kk < 51) ? Wih1[r * 51 + kk] : Whh1[r * 51 + (kk - 51)];
        w2[i] = (kk < 51) ? Wih2[r * 51 + kk] : Whh2[r * 51 + (kk - 51)];
    }
    if (tid < Gg) {
        bias[tid]           = bih0[tid] + bhh0[tid];
        bias[Gg + tid]      = bih1[tid] + bhh1[tid];
        bias[2 * Gg + tid]  = bih2[tid] + bhh2[tid];
    }
    if (tid < 102) wlin[tid] = Wlin[tid];
    if (tid < 2)   blin[tid] = blin_g[tid];
    for (int i = tid; i < 155 * 8; i += NTH) vbuf[i] = 0.0f;
    for (int i = tid; i < 153 * 8; i += NTH) cbuf[i] = 0.0f;
    __syncthreads();

    const bool mv = (local < Gg);
    const float* w0r = w0 + local * NK0;
    const float* w1r = w1 + local * NK;
    const float* w2r = w2 + local * NK;
    const float b0r = mv ? bias[local]          : 0.0f;
    const float b1r = mv ? bias[Gg + local]     : 0.0f;
    const float b2r = mv ? bias[2 * Gg + local] : 0.0f;

    const float* v0 = vbuf;             // rows 0..53  : x | h0 (pad row 53 has weight 0)
    const float* v1 = vbuf + 2 * 8;     // rows 2..103 : h0 | h1
    const float* v2 = vbuf + 53 * 8;    // rows 53..154: h1 | h2
    float* h0 = vbuf + 2 * 8;
    float* h1 = vbuf + 53 * 8;
    float* h2 = vbuf + 104 * 8;
    float* c0 = cbuf;
    float* c1 = cbuf + 408;
    float* c2 = cbuf + 816;

    for (int t = 0; t < Tt; t++) {
        if ((t & (CH - 1)) == 0) {
            // stage next CH timesteps of (input, time) for this half's 4 batches
            {
                int i   = local >> 3;          // timestep within chunk, 0..31
                int rem = local & 7;
                int b   = boff + (rem >> 1);
                int w   = rem & 1;
                const float* src = w ? g_time : g_input;
                xs[(i * 8 + b) * 2 + w] = src[(size_t)(b0g + b) * Tt + t + i];
            }
            hbar(half);
            // copy x for this step (ti = 0) into vbuf rows 0-1
            if (local < 8) {
                int rr = local >> 2, bl = local & 3;
                vbuf[rr * 8 + boff + bl] = xs[(0 * 8 + boff + bl) * 2 + rr];
            }
            hbar(half);
        }

        // cell 0
        if (mv) matvec2<NK0>(local, boff, w0r, v0, b0r, gates);
        hbar(half);
        cellupdate(local, boff, gates, c0, h0);
        hbar(half);
        // cell 1
        if (mv) matvec2<NK>(local, boff, w1r, v1, b1r, gates);
        hbar(half);
        cellupdate(local, boff, gates, c1, h1);
        hbar(half);
        // cell 2
        if (mv) matvec2<NK>(local, boff, w2r, v2, b2r, gates);
        hbar(half);
        cellupdate(local, boff, gates, c2, h2);
        hbar(half);

        // head (8 threads/half) + prefetch next step's x into vbuf rows 0-1
        if (local < 8) {
            int bl = local >> 1, o = local & 1;
            int b  = boff + bl;
            const float* wl = wlin + o * Hh;
            float z = blin[o];
#pragma unroll
            for (int k2 = 0; k2 < Hh; k2++) z = fmaf(wl[k2], h2[k2 * 8 + b], z);
            if (o == 1) z = (z > 30.0f) ? z : log1pf(__expf(z));
            out[(size_t)(b0g + b) * Tt * 2 + (size_t)t * 2 + o] = z;
        } else if (local < 16) {
            int ti1 = (t + 1) & (CH - 1);
            if (ti1 != 0 && (t + 1) < Tt) {   // next step is in the current chunk
                int l2 = local - 8;
                int rr = l2 >> 2, bl = l2 & 3;
                vbuf[rr * 8 + boff + bl] = xs[(ti1 * 8 + boff + bl) * 2 + rr];
            }
        }
        hbar(half);
    }
}

extern "C" void kernel_launch(void* const* d_in, const int* in_sizes, int n_in,
                              void* d_out, int out_size)
{
    const float* input = (const float*)d_in[0];
    const float* timei = (const float*)d_in[1];
    const float* Wih0  = (const float*)d_in[2];
    const float* Whh0  = (const float*)d_in[3];
    const float* bih0  = (const float*)d_in[4];
    const float* bhh0  = (const float*)d_in[5];
    const float* Wih1  = (const float*)d_in[6];
    const float* Whh1  = (const float*)d_in[7];
    const float* bih1  = (const float*)d_in[8];
    const float* bhh1  = (const float*)d_in[9];
    const float* Wih2  = (const float*)d_in[10];
    const float* Whh2  = (const float*)d_in[11];
    const float* bih2  = (const float*)d_in[12];
    const float* bhh2  = (const float*)d_in[13];
    const float* Wlin  = (const float*)d_in[14];
    const float* blin  = (const float*)d_in[15];
    float* out = (float*)d_out;

    cudaFuncSetAttribute(lstm_persistent_kernel,
                         cudaFuncAttributeMaxDynamicSharedMemorySize, SM_BYTES);

    lstm_persistent_kernel<<<NCTA, NTH, SM_BYTES>>>(
        input, timei,
        Wih0, Whh0, bih0, bhh0,
        Wih1, Whh1, bih1, bhh1,
        Wih2, Whh2, bih2, bhh2,
        Wlin, blin, out);
}

// round 4
// speedup vs baseline: 1.1284x; 1.1284x over previous
#include <cuda_runtime.h>

// Problem constants: H=51, L=3, IN=2, B=1024, T=2048
#define Hh    51
#define Gg    204     // 4*H
#define Tt    2048
#define CH    16      // input staging chunk (timesteps)
#define NTH   256
#define NCTA  128     // 1024 / 8 batches per CTA

// Fused state vector (per batch), element indices:
//   0..1   x (input, time)
//   2..52  h0
//   53     1.0 (bias slot for cells 0,1)
//   54..104 h1
//   105    1.0 (bias slot for cell 2)
//   106..156 h2
//   157..159 zero pad
// Pair-packed in smem: vbuf[(e>>1)*16 + b*2 + (e&1)], 80 pairs.
//
// Weights column-major pair-packed: w[kpair*408 + row*2 + par], bias folded.
//   cell0: 27 kpairs (fused els 0..53 = x|h0|bias)
//   cell1: 52 kpairs (fused els = global 2..105 : h0|bias|h1|one-slot(w=0))
//   cell2: 52 kpairs (fused els = global 54..157: h1|bias|h2|pad(w=0))

#define W0_PAIRS 27
#define W12_PAIRS 52

#define OFF_W0    0
#define OFF_W1    (OFF_W0 + W0_PAIRS*408)    // 11016
#define OFF_W2    (OFF_W1 + W12_PAIRS*408)   // 32232
#define OFF_VBUF  (OFF_W2 + W12_PAIRS*408)   // 53448 : 80*16 = 1280
#define OFF_CBUF  (OFF_VBUF + 1280)          // 3 * 408
#define OFF_GATES (OFF_CBUF + 1224)          // 204 * 8
#define OFF_WLIN  (OFF_GATES + 1632)         // 102
#define OFF_BLIN  (OFF_WLIN + 102)           // 2
#define OFF_XS    (OFF_BLIN + 2)             // CH*8*2 = 256
#define SM_FLOATS (OFF_XS + CH*8*2)          // 57944
#define SM_BYTES  (SM_FLOATS * 4)            // 231776 <= 232448

typedef unsigned long long ull;

__device__ __forceinline__ float sigm_f(float x) {
    return __fdividef(1.0f, 1.0f + __expf(-x));
}
__device__ __forceinline__ float tanh_f(float x) {
    return 1.0f - __fdividef(2.0f, __expf(2.0f * x) + 1.0f);
}
__device__ __forceinline__ ull fma2(ull a, ull b, ull c) {
    ull d;
    asm("fma.rn.f32x2 %0, %1, %2, %3;" : "=l"(d) : "l"(a), "l"(b), "l"(c));
    return d;
}
// sum of the two packed floats
__device__ __forceinline__ float red2(ull a) {
    float lo, hi;
    asm("mov.b64 {%0, %1}, %2;" : "=f"(lo), "=f"(hi) : "l"(a));
    return lo + hi;
}

// Matvec: thread rp (0..101) computes gate rows 2rp, 2rp+1 for 8 batches.
// wcol: [P][204][2] col-major pair-packed. vb: pair-packed state slice.
template<int P>
__device__ __forceinline__ void matvec_r2(
    int rp, const float* __restrict__ wcol,
    const float* __restrict__ vb, float* __restrict__ gates)
{
    ull acc0[8], acc1[8];
#pragma unroll
    for (int b = 0; b < 8; b++) { acc0[b] = 0ull; acc1[b] = 0ull; }
    const float* wp = wcol + rp * 4;
#pragma unroll
    for (int kp = 0; kp < P; kp++) {
        ulonglong2 w = *(const ulonglong2*)(wp + kp * 408);   // LDS.128: rows 2rp,2rp+1 pair
        const float* vrow = vb + kp * 16;
#pragma unroll
        for (int b4 = 0; b4 < 4; b4++) {
            ulonglong2 v = *(const ulonglong2*)(vrow + b4 * 4);  // LDS.128 broadcast: batches 2b4,2b4+1
            acc0[2*b4]   = fma2(w.x, v.x, acc0[2*b4]);
            acc0[2*b4+1] = fma2(w.x, v.y, acc0[2*b4+1]);
            acc1[2*b4]   = fma2(w.y, v.x, acc1[2*b4]);
            acc1[2*b4+1] = fma2(w.y, v.y, acc1[2*b4+1]);
        }
    }
    float4 g;
    g = make_float4(red2(acc0[0]), red2(acc0[1]), red2(acc0[2]), red2(acc0[3]));
    *(float4*)(gates + (2*rp) * 8)     = g;
    g = make_float4(red2(acc0[4]), red2(acc0[5]), red2(acc0[6]), red2(acc0[7]));
    *(float4*)(gates + (2*rp) * 8 + 4) = g;
    g = make_float4(red2(acc1[0]), red2(acc1[1]), red2(acc1[2]), red2(acc1[3]));
    *(float4*)(gates + (2*rp+1) * 8)     = g;
    g = make_float4(red2(acc1[4]), red2(acc1[5]), red2(acc1[6]), red2(acc1[7]));
    *(float4*)(gates + (2*rp+1) * 8 + 4) = g;
}

__device__ __forceinline__ void cellup(int el, const float* __restrict__ gates,
                                       float* __restrict__ c, float* __restrict__ vbuf,
                                       int base_e)
{
    float gi = gates[el], gf = gates[408 + el], gg = gates[816 + el], go = gates[1224 + el];
    float cn = sigm_f(gf) * c[el] + sigm_f(gi) * tanh_f(gg);
    c[el] = cn;
    int jj = el >> 3, b = el & 7, e = base_e + jj;
    vbuf[(e >> 1) * 16 + 2 * b + (e & 1)] = sigm_f(go) * tanh_f(cn);
}

__device__ __forceinline__ void head_out(int hid, const float* __restrict__ vbuf,
                                         const float* __restrict__ wlin,
                                         const float* __restrict__ blin,
                                         float* __restrict__ out, int b0g, int t)
{
    int b = hid >> 1, o = hid & 1;
    float z = blin[o];
#pragma unroll
    for (int k = 0; k < Hh; k++) {
        int e = 106 + k;
        z = fmaf(wlin[o * Hh + k], vbuf[(e >> 1) * 16 + 2 * b + (e & 1)], z);
    }
    if (o == 1) z = (z > 30.0f) ? z : log1pf(__expf(z));
    out[(size_t)(b0g + b) * (Tt * 2) + (size_t)t * 2 + o] = z;
}

__global__ void __launch_bounds__(NTH, 1) lstm_persistent_kernel(
    const float* __restrict__ g_input, const float* __restrict__ g_time,
    const float* __restrict__ Wih0, const float* __restrict__ Whh0,
    const float* __restrict__ bih0, const float* __restrict__ bhh0,
    const float* __restrict__ Wih1, const float* __restrict__ Whh1,
    const float* __restrict__ bih1, const float* __restrict__ bhh1,
    const float* __restrict__ Wih2, const float* __restrict__ Whh2,
    const float* __restrict__ bih2, const float* __restrict__ bhh2,
    const float* __restrict__ Wlin, const float* __restrict__ blin_g,
    float* __restrict__ out)
{
    extern __shared__ float sm[];
    float* w0    = sm + OFF_W0;
    float* w1    = sm + OFF_W1;
    float* w2    = sm + OFF_W2;
    float* vbuf  = sm + OFF_VBUF;
    float* cbuf  = sm + OFF_CBUF;
    float* gates = sm + OFF_GATES;
    float* wlin  = sm + OFF_WLIN;
    float* blin  = sm + OFF_BLIN;
    float* xs    = sm + OFF_XS;

    const int tid = threadIdx.x;
    const int b0g = blockIdx.x * 8;

    // ---- build column-major pair-packed weights (bias folded at constant-1 slots) ----
    for (int i = tid; i < Gg * 54; i += NTH) {
        int r = i / 54, e = i % 54;
        float v;
        if (e < 2)       v = Wih0[r * 2 + e];
        else if (e < 53) v = Whh0[r * Hh + (e - 2)];
        else             v = bih0[r] + bhh0[r];
        w0[(e >> 1) * 408 + r * 2 + (e & 1)] = v;
    }
    for (int i = tid; i < Gg * 104; i += NTH) {
        int r = i / 104, e = i % 104;
        float a, b;
        if (e < 51)       { a = Wih1[r * Hh + e];        b = Wih2[r * Hh + e]; }
        else if (e == 51) { a = bih1[r] + bhh1[r];       b = bih2[r] + bhh2[r]; }
        else if (e < 103) { a = Whh1[r * Hh + (e - 52)]; b = Whh2[r * Hh + (e - 52)]; }
        else              { a = 0.0f;                    b = 0.0f; }
        int off = (e >> 1) * 408 + r * 2 + (e & 1);
        w1[off] = a; w2[off] = b;
    }
    if (tid < 102) wlin[tid] = Wlin[tid];
    if (tid < 2)   blin[tid] = blin_g[tid];
    for (int i = tid; i < 1280; i += NTH) vbuf[i] = 0.0f;
    for (int i = tid; i < 1224; i += NTH) cbuf[i] = 0.0f;
    __syncthreads();
    if (tid < 8) {
        vbuf[26 * 16 + tid * 2 + 1] = 1.0f;   // element 53  = 1.0 (bias cells 0,1)
        vbuf[52 * 16 + tid * 2 + 1] = 1.0f;   // element 105 = 1.0 (bias cell 2)
    }
    __syncthreads();

    float* c0 = cbuf;
    float* c1 = cbuf + 408;
    float* c2 = cbuf + 816;

    for (int t = 0; t < Tt; t++) {
        if ((t & (CH - 1)) == 0) {
            // stage CH timesteps: 256 elements, one per thread
            int ti = tid >> 4, rem = tid & 15, b = rem >> 1, f = rem & 1;
            const float* src = f ? g_time : g_input;
            xs[(ti * 8 + b) * 2 + f] = src[(size_t)(b0g + b) * Tt + t + ti];
            __syncthreads();
            if (tid < 16) {   // copy x(t) into vbuf pair 0
                int bb = tid >> 1, ff = tid & 1;
                vbuf[2 * bb + ff] = xs[bb * 2 + ff];
            }
            __syncthreads();
        }

        // phase A: cell0 matvec || head(t-1)
        if (tid < 102)                         matvec_r2<W0_PAIRS>(tid, w0, vbuf, gates);
        else if (t > 0 && tid >= 128 && tid < 144)
            head_out(tid - 128, vbuf, wlin, blin, out, b0g, t - 1);
        __syncthreads();
        if (tid < 204) { cellup(tid, gates, c0, vbuf, 2); cellup(tid + 204, gates, c0, vbuf, 2); }
        __syncthreads();

        // cell1
        if (tid < 102) matvec_r2<W12_PAIRS>(tid, w1, vbuf + 16, gates);
        __syncthreads();
        if (tid < 204) { cellup(tid, gates, c1, vbuf, 54); cellup(tid + 204, gates, c1, vbuf, 54); }
        __syncthreads();

        // cell2 matvec || x(t+1) prefetch
        if (tid < 102) matvec_r2<W12_PAIRS>(tid, w2, vbuf + 27 * 16, gates);
        else if (tid >= 144 && tid < 160) {
            int ti1 = (t + 1) & (CH - 1);
            if (ti1 != 0) {   // next step within current chunk
                int l2 = tid - 144, bb = l2 >> 1, ff = l2 & 1;
                vbuf[2 * bb + ff] = xs[(ti1 * 8 + bb) * 2 + ff];
            }
        }
        __syncthreads();
        if (tid < 204) { cellup(tid, gates, c2, vbuf, 106); cellup(tid + 204, gates, c2, vbuf, 106); }
        __syncthreads();
    }

    // final head for t = Tt-1
    if (tid >= 128 && tid < 144)
        head_out(tid - 128, vbuf, wlin, blin, out, b0g, Tt - 1);
}

extern "C" void kernel_launch(void* const* d_in, const int* in_sizes, int n_in,
                              void* d_out, int out_size)
{
    const float* input = (const float*)d_in[0];
    const float* timei = (const float*)d_in[1];
    const float* Wih0  = (const float*)d_in[2];
    const float* Whh0  = (const float*)d_in[3];
    const float* bih0  = (const float*)d_in[4];
    const float* bhh0  = (const float*)d_in[5];
    const float* Wih1  = (const float*)d_in[6];
    const float* Whh1  = (const float*)d_in[7];
    const float* bih1  = (const float*)d_in[8];
    const float* bhh1  = (const float*)d_in[9];
    const float* Wih2  = (const float*)d_in[10];
    const float* Whh2  = (const float*)d_in[11];
    const float* bih2  = (const float*)d_in[12];
    const float* bhh2  = (const float*)d_in[13];
    const float* Wlin  = (const float*)d_in[14];
    const float* blin  = (const float*)d_in[15];
    float* out = (float*)d_out;

    cudaFuncSetAttribute(lstm_persistent_kernel,
                         cudaFuncAttributeMaxDynamicSharedMemorySize, SM_BYTES);

    lstm_persistent_kernel<<<NCTA, NTH, SM_BYTES>>>(
        input, timei,
        Wih0, Whh0, bih0, bhh0,
        Wih1, Whh1, bih1, bhh1,
        Wih2, Whh2, bih2, bhh2,
        Wlin, blin, out);
}